// round 11
// baseline (speedup 1.0000x reference)
#include <cuda_runtime.h>
#include <math.h>

#define CC   256
#define HH   40
#define WW   40
#define NROI 64
#define PHB  7
#define PWB  7
#define HW   1600
#define NBLK 512

// dynamic smem: rbuf[8 warps][7 ph][4 ch][40]
#define RB_PH  (4 * 40)
#define RB_W   (7 * RB_PH)
#define SMEM_DYN (8 * RB_W * 4)

// persistent scratch (no device allocs allowed)
__device__ float g_s[HW];
__device__ float g_maskeff[NROI * HW];   // per-ROI effective mask (replay-invariant)
__device__ int   g_smax_bits;            // float bits; s>0 -> int-max == float-max
__device__ int   g_cnt;                  // barrier 1 counter (monotonic, never reset)
__device__ int   g_cnt2;                 // barrier 2 counter (monotonic, never reset)

struct Roi {
    int x1a, y1a, x2a, y2a, x1b, y1b, x2b, y2b;
    int ux1, uy1, ux2, uy2, hb, wb;
};

// round-half-even (matches jnp.round); clamp upper side only
__device__ __forceinline__ Roi roi_decode(const float* __restrict__ r1,
                                          const float* __restrict__ r2, int n) {
    const float* a = r1 + n * 5;
    const float* b = r2 + n * 5;
    Roi r;
    r.x1a = min(__float2int_rn(a[1] * 0.0625f), WW - 1);
    r.y1a = min(__float2int_rn(a[2] * 0.0625f), HH - 1);
    r.x2a = min(__float2int_rn(a[3] * 0.0625f), WW - 1);
    r.y2a = min(__float2int_rn(a[4] * 0.0625f), HH - 1);
    r.x1b = min(__float2int_rn(b[1] * 0.0625f), WW - 1);
    r.y1b = min(__float2int_rn(b[2] * 0.0625f), HH - 1);
    r.x2b = min(__float2int_rn(b[3] * 0.0625f), WW - 1);
    r.y2b = min(__float2int_rn(b[4] * 0.0625f), HH - 1);
    r.ux1 = min(r.x1a, r.x1b); r.uy1 = min(r.y1a, r.y1b);
    r.ux2 = max(r.x2a, r.x2b); r.uy2 = max(r.y2a, r.y2b);
    r.hb = r.uy2 - r.uy1 + 1;
    r.wb = r.ux2 - r.ux1 + 1;
    return r;
}

// ---------------------------------------------------------------------------
// Persistent fused kernel. 512 blocks x 256 threads, 4/SM -> all resident.
// Phase A (blocks 0..199): channel sums + smax.    barrier 1.
// Phase M (all blocks, 8 per ROI): eff-mask -> global g_maskeff.  barrier 2.
// Pool: ONE item = (ROI, 4 ch) per WARP; item map quad=gwid>>6,
// n=(gwid^quad)&63 decorrelates ROIs across each SM's 32 warps -> per-SM
// work variance ~9% (attacks the measured 40%-occupancy idle tail).
// ---------------------------------------------------------------------------
__global__ void __launch_bounds__(256, 4)
k_fused(const float* __restrict__ fm,
        const float* __restrict__ rois1,
        const float* __restrict__ rois2,
        float* __restrict__ out) {
    extern __shared__ float sm[];
    __shared__ float sred[64];
    const int bid = blockIdx.x;
    const int t   = threadIdx.x;
    const int w   = t >> 5, l = t & 31;
    float* rb = sm + w * RB_W;              // this warp's [7][4][40]

    // ---- Phase A: channel sums for pixels [bid*8, bid*8+8) (blocks 0..199)
    if (bid < 200) {
        const int px = t & 7;
        const int cs = t >> 3;              // 0..31, 8 channels each
        const float* f = fm + cs * 8 * HW + bid * 8 + px;
        float s = f[0] + f[HW] + f[2 * HW] + f[3 * HW]
                + f[4 * HW] + f[5 * HW] + f[6 * HW] + f[7 * HW];
        s += __shfl_down_sync(0xffffffffu, s, 16);
        s += __shfl_down_sync(0xffffffffu, s, 8);
        if (l < 8) sred[w * 8 + l] = s;     // [warp][px]
        __syncthreads();
        if (t < 8) {
            float acc = 0.f;
#pragma unroll
            for (int ww = 0; ww < 8; ww++) acc += sred[ww * 8 + t];
            g_s[bid * 8 + t] = acc;
#pragma unroll
            for (int o = 4; o; o >>= 1)
                acc = fmaxf(acc, __shfl_down_sync(0xffu, acc, o));
            if (t == 0) atomicMax(&g_smax_bits, __float_as_int(acc));
            __threadfence();                // release g_s / smax stores
        }
    }
    __syncthreads();                        // order fences before barrier arrival

    // ---- barrier 1 (stateless monotonic) ----
    if (t == 0) {
        int ticket = atomicAdd(&g_cnt, 1);
        int target = (ticket / NBLK + 1) * NBLK;
        while (*(volatile int*)&g_cnt < target) { }
    }
    __syncthreads();

    const float smax = __int_as_float(*(volatile int*)&g_smax_bits);
    const float inv  = 1.0f / smax;

    // ---- Phase M: build g_maskeff; 8 blocks per ROI, 200 px each ----
    {
        const int mn = bid >> 3;
        Roi r = roi_decode(rois1, rois2, mn);
        if (t < 200) {
            const int p = (bid & 7) * 200 + t;
            const int y = p / WW, x = p % WW;
            bool inA = (x >= r.x1a) & (x <= r.x2a) & (y >= r.y1a) & (y <= r.y2a);
            bool inB = (x >= r.x1b) & (x <= r.x2b) & (y >= r.y1b) & (y <= r.y2b);
            float s  = g_s[p];
            float xx = s * inv;
            float x2 = xx * xx;
            g_maskeff[mn * HW + p] = (inA || inB) ? 1.0f : (0.5f + 0.4f * (x2 * x2));
            __threadfence();                // release mask stores
        }
    }
    __syncthreads();

    // ---- barrier 2 (stateless monotonic) ----
    if (t == 0) {
        int ticket = atomicAdd(&g_cnt2, 1);
        int target = (ticket / NBLK + 1) * NBLK;
        while (*(volatile int*)&g_cnt2 < target) { }
    }
    __syncthreads();

    // ---- pool: one (ROI, 4ch) item per warp, XOR-mixed assignment ----
    const int gwid = bid * 8 + w;
    const int quad = gwid >> 6;             // 0..63 -> c0
    const int n    = (gwid ^ quad) & 63;    // bijective with quad; decorrelated
    Roi r = roi_decode(rois1, rois2, n);
    const int uy1 = r.uy1, hb = r.hb, wb = r.wb;
    const int c0 = quad * 4;
    const int xg = r.ux1 + l;
    const bool wide = (wb > 32);
    const float* cbase = fm + c0 * HW;
    const float* gm    = g_maskeff + n * HW;

#pragma unroll
    for (int ph = 0; ph < PHB; ph++) {
        int ys = uy1 + (ph * hb) / 7;
        int ye = uy1 + ((ph + 1) * hb + 6) / 7;
        const float* p0 = cbase + ys * WW + xg;
        const float* mp = gm + ys * WW + xg;
        float a0 = -INFINITY, a1 = -INFINITY, a2 = -INFINITY, a3 = -INFINITY;
        float* rphp = rb + ph * RB_PH;

        if (!wide) {
            if (l < wb) {
                int y = ys;
                for (; y + 1 < ye; y += 2) {           // 10 independent LDGs
                    float m0 = mp[0], m1 = mp[WW];
                    float u0 = p0[0],           u1 = p0[HW];
                    float u2 = p0[2 * HW],      u3 = p0[3 * HW];
                    float v0 = p0[WW],          v1 = p0[HW + WW];
                    float v2 = p0[2 * HW + WW], v3 = p0[3 * HW + WW];
                    a0 = fmaxf(fmaxf(a0, u0 * m0), v0 * m1);
                    a1 = fmaxf(fmaxf(a1, u1 * m0), v1 * m1);
                    a2 = fmaxf(fmaxf(a2, u2 * m0), v2 * m1);
                    a3 = fmaxf(fmaxf(a3, u3 * m0), v3 * m1);
                    p0 += 2 * WW; mp += 2 * WW;
                }
                if (y < ye) {
                    float m0 = mp[0];
                    a0 = fmaxf(a0, p0[0]      * m0);
                    a1 = fmaxf(a1, p0[HW]     * m0);
                    a2 = fmaxf(a2, p0[2 * HW] * m0);
                    a3 = fmaxf(a3, p0[3 * HW] * m0);
                }
            }
            rphp[0 * 40 + l] = a0; rphp[1 * 40 + l] = a1;
            rphp[2 * 40 + l] = a2; rphp[3 * 40 + l] = a3;
        } else {
            float b0 = -INFINITY, b1 = -INFINITY, b2 = -INFINITY, b3 = -INFINITY;
            const bool act1 = (l + 32 < wb);
            for (int y = ys; y < ye; y++) {            // 10 independent LDGs
                float m0 = mp[0];
                a0 = fmaxf(a0, p0[0]      * m0);
                a1 = fmaxf(a1, p0[HW]     * m0);
                a2 = fmaxf(a2, p0[2 * HW] * m0);
                a3 = fmaxf(a3, p0[3 * HW] * m0);
                if (act1) {
                    float m1 = mp[32];
                    b0 = fmaxf(b0, p0[32]          * m1);
                    b1 = fmaxf(b1, p0[HW + 32]     * m1);
                    b2 = fmaxf(b2, p0[2 * HW + 32] * m1);
                    b3 = fmaxf(b3, p0[3 * HW + 32] * m1);
                }
                p0 += WW; mp += WW;
            }
            rphp[0 * 40 + l] = a0; rphp[1 * 40 + l] = a1;
            rphp[2 * 40 + l] = a2; rphp[3 * 40 + l] = a3;
            if (l + 32 < 40) {
                rphp[0 * 40 + l + 32] = b0; rphp[1 * 40 + l + 32] = b1;
                rphp[2 * 40 + l + 32] = b2; rphp[3 * 40 + l + 32] = b3;
            }
        }
    }

    __syncwarp();

    // ---- epilogue: bin reduces (lanes 0..27 -> (channel, pw-bin)) ----
    if (l < 28) {
        const int rci = l / 7;
        const int rpw = l - rci * 7;
        const int xs = (rpw * wb) / 7;
        const int xe = ((rpw + 1) * wb + 6) / 7;
        float* outn = out + (n * CC + c0 + rci) * (PHB * PWB) + rpw;
        const float* rc = rb + rci * 40;
#pragma unroll
        for (int ph = 0; ph < PHB; ph++) {
            const float* r2 = rc + ph * RB_PH;
            float mx = -INFINITY;
            for (int x = xs; x < xe; x++) mx = fmaxf(mx, r2[x]);
            outn[ph * PWB] = mx;
        }
    }
}

// ---------------------------------------------------------------------------
extern "C" void kernel_launch(void* const* d_in, const int* in_sizes, int n_in,
                              void* d_out, int out_size) {
    const float* fm = (const float*)d_in[0];
    const float* r1 = (const float*)d_in[1];
    const float* r2 = (const float*)d_in[2];
    float* out = (float*)d_out;

    cudaFuncSetAttribute(k_fused, cudaFuncAttributeMaxDynamicSharedMemorySize, SMEM_DYN);
    k_fused<<<NBLK, 256, SMEM_DYN>>>(fm, r1, r2, out);
}